// round 15
// baseline (speedup 1.0000x reference)
#include <cuda_runtime.h>
#include <cuda_bf16.h>
#include <cuda_fp16.h>
#include <cstdint>

#define D 128
#define NMAX 100000
#define EMAX 800000
#define NBMAX 128   // ceil(NMAX/1024)
#define WPAD 136    // padded bf16 row stride (272B): conflict-free fragments

// -------- scratch (device globals; no allocations allowed) --------
__device__ __half g_hh[(size_t)NMAX * D]; // x @ W^T, fp16 storage (256B/row)
__device__ float g_deg[NMAX];
__device__ float g_dinv[NMAX];
__device__ int   g_rows[EMAX];
__device__ int   g_cols[EMAX];
__device__ int   g_sr[EMAX];              // row ids sorted by destination col
__device__ int   g_off[NMAX + 1];         // CSR offsets (by col)
__device__ int   g_cursor[NMAX];
__device__ int   g_bsum[NBMAX];
__device__ int   g_bpre[NBMAX];
__device__ float g_sum[D];
__device__ float g_sumsq[D];
__device__ float g_mean[D];
__device__ float g_scale[D];
__device__ int   g_is64;
__device__ int   g_ctrB;                  // agg grid-barrier counter
__device__ volatile int g_go;             // agg grid-barrier release flag
__device__ int   eb_ctr;                  // edge-kernel barrier counter (0-init)
__device__ int   eb_gen;                  // edge-kernel barrier generation
__device__ __align__(16) __nv_bfloat16 g_whi[128 * WPAD];  // W hi, padded
__device__ __align__(16) __nv_bfloat16 g_wlo[128 * WPAD];  // W lo, padded

// ---- generation-based grid barrier (all blocks resident by construction) --
__device__ __forceinline__ void grid_bar() {
    __syncthreads();
    if (threadIdx.x == 0) {
        __threadfence();                         // publish this phase's writes
        int g = *(volatile int*)&eb_gen;         // read gen BEFORE arrival
        if (atomicAdd(&eb_ctr, 1) == (int)gridDim.x - 1) {
            eb_ctr = 0;
            __threadfence();
            *(volatile int*)&eb_gen = g + 1;
        } else {
            while (*(volatile int*)&eb_gen == g) __nanosleep(64);
        }
        __threadfence();                         // acquire
    }
    __syncthreads();
}

// ==== persistent edge pipeline: zero+detect -> convert+deg -> scan -> ======
// ==== tile-sum scan -> offsets+cursor+dinv -> bucket, one kernel ===========
__global__ __launch_bounds__(256, 8)
void edge_kernel(const void* __restrict__ ei, int n, int E, int ntiles) {
    __shared__ int wsum[8];
    __shared__ int sscan[NBMAX];
    int t = threadIdx.x;
    int lane = t & 31, w = t >> 5;
    int bid = blockIdx.x;
    int gstride = gridDim.x * 256;
    int gtid = bid * 256 + t;

    // ---- P0: zero deg/BN sums, reset agg ctrs, warp-parallel dtype detect --
    for (int i = gtid; i < n; i += gstride) g_deg[i] = 0.f;
    if (gtid < D) { g_sum[gtid] = 0.f; g_sumsq[gtid] = 0.f; }
    if (gtid == 0) { g_ctrB = 0; g_go = 0; }
    if (bid == 0 && t < 32) {
        // Node ids < 2^31: int64 layout => every odd 32-bit word is 0.
        const unsigned int* wp = (const unsigned int*)ei;
        unsigned int a = wp[2 * t + 1];
        unsigned int b = wp[2 * t + 65];
        unsigned int nz = __ballot_sync(0xFFFFFFFFu, (a | b) != 0u);
        if (t == 0) g_is64 = (nz == 0u) ? 1 : 0;
    }
    grid_bar();

    // ---- P1: convert edges to int32 staging + degree histogram ----
    {
        int is64 = g_is64;
        for (int e = gtid; e < E; e += gstride) {
            int r, c;
            if (is64) {
                const long long* p = (const long long*)ei;
                r = (int)p[e];
                c = (int)p[(size_t)E + e];
            } else {
                const int* p = (const int*)ei;
                r = p[e];
                c = p[(size_t)E + e];
            }
            g_rows[e] = r;
            g_cols[e] = c;
            atomicAdd(&g_deg[c], 1.0f);
        }
    }
    grid_bar();

    // ---- P2: per-tile (1024 elems) coalesced scan: in-tile prefix + sums ---
    for (int tile = bid; tile < ntiles; tile += gridDim.x) {
        int base = tile * 1024 + t * 4;
        int v0 = 0, v1 = 0, v2 = 0, v3 = 0;
        if (base + 3 < n) {
            float4 f = *(const float4*)(g_deg + base);
            v0 = (int)f.x; v1 = (int)f.y; v2 = (int)f.z; v3 = (int)f.w;
        } else {
            if (base + 0 < n) v0 = (int)g_deg[base + 0];
            if (base + 1 < n) v1 = (int)g_deg[base + 1];
            if (base + 2 < n) v2 = (int)g_deg[base + 2];
            if (base + 3 < n) v3 = (int)g_deg[base + 3];
        }
        int ts = v0 + v1 + v2 + v3;

        int incl = ts;
        #pragma unroll
        for (int d = 1; d < 32; d <<= 1) {
            int u = __shfl_up_sync(0xFFFFFFFFu, incl, d);
            if (lane >= d) incl += u;
        }
        if (lane == 31) wsum[w] = incl;
        __syncthreads();
        if (t == 0) {
            int run = 0;
            #pragma unroll
            for (int i = 0; i < 8; i++) { int x = wsum[i]; wsum[i] = run; run += x; }
        }
        __syncthreads();

        int ex = wsum[w] + incl - ts;
        if (base + 3 < n) {
            *(int4*)(g_off + base) = make_int4(ex, ex + v0, ex + v0 + v1, ex + v0 + v1 + v2);
        } else {
            if (base + 0 < n) g_off[base + 0] = ex;
            if (base + 1 < n) g_off[base + 1] = ex + v0;
            if (base + 2 < n) g_off[base + 2] = ex + v0 + v1;
            if (base + 3 < n) g_off[base + 3] = ex + v0 + v1 + v2;
        }
        if (t == 255) g_bsum[tile] = wsum[7] + incl;
        __syncthreads();   // wsum reuse across tile iterations
    }
    grid_bar();

    // ---- P3: block 0 scans the <=128 tile sums ----
    if (bid == 0) {
        if (t < ntiles) sscan[t] = g_bsum[t];
        __syncthreads();
        if (t == 0) {
            int run = 0;
            for (int i = 0; i < ntiles; i++) { int v = sscan[i]; sscan[i] = run; run += v; }
        }
        __syncthreads();
        if (t < ntiles) g_bpre[t] = sscan[t];
    }
    grid_bar();

    // ---- P4: global offsets + cursor init + dinv ----
    for (int i = gtid; i < n; i += gstride) {
        int off = g_off[i] + g_bpre[i >> 10];
        g_off[i] = off;
        g_cursor[i] = off;
        float d = g_deg[i];
        g_dinv[i] = (d > 0.f) ? rsqrtf(d) : 0.f;
    }
    if (gtid == 0) g_off[n] = E;
    grid_bar();

    // ---- P5: bucket edges by destination col ----
    for (int e = gtid; e < E; e += gstride) {
        int c = g_cols[e];
        int pos = atomicAdd(&g_cursor[c], 1);
        g_sr[pos] = g_rows[e];
    }
}

// ======== GEMM via mma.sync bf16 (3-term hi/lo split, fp32 accum) =========
__global__ void prep_w_kernel(const float* __restrict__ W) {
    int i = blockIdx.x * blockDim.x + threadIdx.x;
    if (i >= 128 * 128) return;
    int r = i >> 7, k = i & 127;
    float v = W[i];
    __nv_bfloat16 h = __float2bfloat16(v);
    g_whi[r * WPAD + k] = h;
    g_wlo[r * WPAD + k] = __float2bfloat16(v - __bfloat162float(h));
}

__device__ __forceinline__ void mma16816(float* c, const uint32_t* a,
                                         uint32_t b0, uint32_t b1) {
    asm volatile(
        "mma.sync.aligned.m16n8k16.row.col.f32.bf16.bf16.f32 "
        "{%0,%1,%2,%3}, {%4,%5,%6,%7}, {%8,%9}, {%0,%1,%2,%3};"
        : "+f"(c[0]), "+f"(c[1]), "+f"(c[2]), "+f"(c[3])
        : "r"(a[0]), "r"(a[1]), "r"(a[2]), "r"(a[3]), "r"(b0), "r"(b1));
}

#define SM_WHI 0
#define SM_WLO (128 * WPAD)
#define SM_XHI (2 * 128 * WPAD)
#define SM_XLO (3 * 128 * WPAD)
#define GEMM_SMEM (4 * 128 * WPAD * 2)   // 139264 bytes

__global__ __launch_bounds__(256, 1)
void gemm_mma_kernel(const float* __restrict__ x, int n) {
    extern __shared__ __nv_bfloat16 smem[];
    int t = threadIdx.x;
    int row0 = blockIdx.x * 128;

    {
        const uint4* srcH = (const uint4*)g_whi;
        const uint4* srcL = (const uint4*)g_wlo;
        uint4* dstH = (uint4*)(smem + SM_WHI);
        uint4* dstL = (uint4*)(smem + SM_WLO);
        #pragma unroll
        for (int i = t; i < 2176; i += 256) { dstH[i] = srcH[i]; dstL[i] = srcL[i]; }
    }
    #pragma unroll
    for (int i = t; i < 4096; i += 256) {
        int r = i >> 5, c4 = (i & 31) << 2;
        int gr = row0 + r;
        float4 v = make_float4(0.f, 0.f, 0.f, 0.f);
        if (gr < n) v = *(const float4*)(x + (size_t)gr * D + c4);
        __nv_bfloat16 h0 = __float2bfloat16(v.x), h1 = __float2bfloat16(v.y);
        __nv_bfloat16 h2 = __float2bfloat16(v.z), h3 = __float2bfloat16(v.w);
        __nv_bfloat162* ph = (__nv_bfloat162*)(smem + SM_XHI + r * WPAD + c4);
        __nv_bfloat162* pl = (__nv_bfloat162*)(smem + SM_XLO + r * WPAD + c4);
        ph[0] = __nv_bfloat162(h0, h1);
        ph[1] = __nv_bfloat162(h2, h3);
        pl[0] = __nv_bfloat162(__float2bfloat16(v.x - __bfloat162float(h0)),
                               __float2bfloat16(v.y - __bfloat162float(h1)));
        pl[1] = __nv_bfloat162(__float2bfloat16(v.z - __bfloat162float(h2)),
                               __float2bfloat16(v.w - __bfloat162float(h3)));
    }
    __syncthreads();

    int lane = t & 31, wid = t >> 5;
    int wm = wid & 1;
    int wn = wid >> 1;
    int rq = lane >> 2;
    int kq = (lane & 3) << 1;

    float acc[4][4][4] = {};

    #pragma unroll
    for (int ks = 0; ks < 8; ks++) {
        int kb = ks * 16 + kq;
        uint32_t aH[4][4], aL[4][4];
        #pragma unroll
        for (int mi = 0; mi < 4; mi++) {
            int rb = wm * 64 + mi * 16 + rq;
            const __nv_bfloat16* pH = smem + SM_XHI + rb * WPAD + kb;
            const __nv_bfloat16* pL = smem + SM_XLO + rb * WPAD + kb;
            aH[mi][0] = *(const uint32_t*)pH;
            aH[mi][1] = *(const uint32_t*)(pH + 8 * WPAD);
            aH[mi][2] = *(const uint32_t*)(pH + 8);
            aH[mi][3] = *(const uint32_t*)(pH + 8 * WPAD + 8);
            aL[mi][0] = *(const uint32_t*)pL;
            aL[mi][1] = *(const uint32_t*)(pL + 8 * WPAD);
            aL[mi][2] = *(const uint32_t*)(pL + 8);
            aL[mi][3] = *(const uint32_t*)(pL + 8 * WPAD + 8);
        }
        #pragma unroll
        for (int ni = 0; ni < 4; ni++) {
            int nb = wn * 32 + ni * 8 + rq;
            const __nv_bfloat16* pH = smem + SM_WHI + nb * WPAD + kb;
            const __nv_bfloat16* pL = smem + SM_WLO + nb * WPAD + kb;
            uint32_t bH0 = *(const uint32_t*)pH;
            uint32_t bH1 = *(const uint32_t*)(pH + 8);
            uint32_t bL0 = *(const uint32_t*)pL;
            uint32_t bL1 = *(const uint32_t*)(pL + 8);
            #pragma unroll
            for (int mi = 0; mi < 4; mi++) {
                mma16816(acc[mi][ni], aH[mi], bH0, bH1);
                mma16816(acc[mi][ni], aH[mi], bL0, bL1);
                mma16816(acc[mi][ni], aL[mi], bH0, bH1);
            }
        }
    }

    // epilogue: store fp16 (halves agg's read traffic)
    #pragma unroll
    for (int mi = 0; mi < 4; mi++) {
        int r0 = row0 + wm * 64 + mi * 16 + rq;
        #pragma unroll
        for (int ni = 0; ni < 4; ni++) {
            int cc = wn * 32 + ni * 8 + kq;
            if (r0 < n) {
                __half2 hv = __floats2half2_rn(acc[mi][ni][0], acc[mi][ni][1]);
                *(__half2*)(g_hh + (size_t)r0 * D + cc) = hv;
            }
            if (r0 + 8 < n) {
                __half2 hv = __floats2half2_rn(acc[mi][ni][2], acc[mi][ni][3]);
                *(__half2*)(g_hh + (size_t)(r0 + 8) * D + cc) = hv;
            }
        }
    }
}

// ==== persistent agg: gather + BN sums + grid barrier + stats + epilogue ===
__global__ __launch_bounds__(256, 4)
void agg_kernel(float* __restrict__ out, const float* __restrict__ x,
                const float* __restrict__ gamma, const float* __restrict__ beta,
                int n) {
    __shared__ float ss[8][128];
    __shared__ float sq[8][128];
    __shared__ int slast;
    int t = threadIdx.x;
    int w = t >> 5, lane = t & 31;
    int stride = gridDim.x * 8;
    int c4 = lane << 2;

    // ---- phase 1: gather + per-warp BN partial sums ----
    float4 csum = make_float4(0.f, 0.f, 0.f, 0.f);
    float4 csq  = make_float4(0.f, 0.f, 0.f, 0.f);

    for (int c = blockIdx.x * 8 + w; c < n; c += stride) {
        int beg = g_off[c], end = g_off[c + 1];
        float dc = g_dinv[c];
        float4 acc = make_float4(0.f, 0.f, 0.f, 0.f);

        int j = beg;
        for (; j + 1 < end; j += 2) {
            int r0 = g_sr[j], r1 = g_sr[j + 1];
            float n0 = dc * g_dinv[r0];
            float n1 = dc * g_dinv[r1];
            uint2 u0 = *((const uint2*)(g_hh + ((size_t)r0 << 7)) + lane);
            uint2 u1 = *((const uint2*)(g_hh + ((size_t)r1 << 7)) + lane);
            float2 a0 = __half22float2(*(__half2*)&u0.x);
            float2 b0 = __half22float2(*(__half2*)&u0.y);
            float2 a1 = __half22float2(*(__half2*)&u1.x);
            float2 b1 = __half22float2(*(__half2*)&u1.y);
            acc.x += a0.x * n0 + a1.x * n1;
            acc.y += a0.y * n0 + a1.y * n1;
            acc.z += b0.x * n0 + b1.x * n1;
            acc.w += b0.y * n0 + b1.y * n1;
        }
        if (j < end) {
            int r0 = g_sr[j];
            float n0 = dc * g_dinv[r0];
            uint2 u0 = *((const uint2*)(g_hh + ((size_t)r0 << 7)) + lane);
            float2 a0 = __half22float2(*(__half2*)&u0.x);
            float2 b0 = __half22float2(*(__half2*)&u0.y);
            acc.x += a0.x * n0; acc.y += a0.y * n0;
            acc.z += b0.x * n0; acc.w += b0.y * n0;
        }
        *(float4*)(out + ((size_t)c << 7) + c4) = acc;
        csum.x += acc.x; csum.y += acc.y; csum.z += acc.z; csum.w += acc.w;
        csq.x += acc.x * acc.x; csq.y += acc.y * acc.y;
        csq.z += acc.z * acc.z; csq.w += acc.w * acc.w;
    }

    ss[w][c4 + 0] = csum.x; ss[w][c4 + 1] = csum.y;
    ss[w][c4 + 2] = csum.z; ss[w][c4 + 3] = csum.w;
    sq[w][c4 + 0] = csq.x;  sq[w][c4 + 1] = csq.y;
    sq[w][c4 + 2] = csq.z;  sq[w][c4 + 3] = csq.w;
    __syncthreads();
    if (t < 128) {
        float s = 0.f, s2 = 0.f;
        #pragma unroll
        for (int i = 0; i < 8; i++) { s += ss[i][t]; s2 += sq[i][t]; }
        atomicAdd(&g_sum[t], s);
        atomicAdd(&g_sumsq[t], s2);
    }

    // ---- grid barrier (all blocks resident by construction) ----
    __threadfence();
    __syncthreads();
    if (t == 0)
        slast = (atomicAdd(&g_ctrB, 1) == (int)gridDim.x - 1) ? 1 : 0;
    __syncthreads();
    if (slast) {
        if (t < 128) {
            float inv_n = 1.0f / (float)n;
            float mean = g_sum[t] * inv_n;
            float var = g_sumsq[t] * inv_n - mean * mean;
            g_mean[t] = mean;               // linear bias cancels via mean subtraction
            g_scale[t] = rsqrtf(var + 1e-5f) * gamma[t];
        }
        __threadfence();
        __syncthreads();
        if (t == 0) g_go = 1;
    }
    if (t == 0) { while (g_go == 0) __nanosleep(64); }
    __syncthreads();
    __threadfence();   // acquire: order g_mean/g_scale reads after flag

    // ---- phase 2: epilogue over this warp's own nodes (out rows L2-hot) ---
    float4 mn = *(const float4*)(g_mean + c4);
    float4 sc = *(const float4*)(g_scale + c4);
    float4 bt = *(const float4*)(beta + c4);
    for (int c = blockIdx.x * 8 + w; c < n; c += stride) {
        float4 a = *(float4*)(out + ((size_t)c << 7) + c4);
        float4 xv = *(const float4*)(x + (size_t)c * D + c4);
        a.x = fmaxf((a.x - mn.x) * sc.x + bt.x, 0.f) + xv.x;
        a.y = fmaxf((a.y - mn.y) * sc.y + bt.y, 0.f) + xv.y;
        a.z = fmaxf((a.z - mn.z) * sc.z + bt.z, 0.f) + xv.z;
        a.w = fmaxf((a.w - mn.w) * sc.w + bt.w, 0.f) + xv.w;
        *(float4*)(out + ((size_t)c << 7) + c4) = a;
    }
}

extern "C" void kernel_launch(void* const* d_in, const int* in_sizes, int n_in,
                              void* d_out, int out_size) {
    const float* x     = (const float*)d_in[0];
    const void*  ei    = d_in[1];
    const float* W     = (const float*)d_in[2];
    const float* gamma = (const float*)d_in[4];
    const float* beta  = (const float*)d_in[5];
    int n = in_sizes[0] / D;
    int E = in_sizes[1] / 2;
    float* out = (float*)d_out;

    // residency-safe grids for the persistent kernels (computed once;
    // occupancy/attribute queries are not stream ops — capture-safe)
    static int agg_grid = 0, edge_grid = 0;
    if (agg_grid == 0) {
        int dev = 0, nsm = 0, bps = 0;
        cudaGetDevice(&dev);
        cudaDeviceGetAttribute(&nsm, cudaDevAttrMultiProcessorCount, dev);
        cudaOccupancyMaxActiveBlocksPerMultiprocessor(&bps, agg_kernel, 256, 0);
        if (bps < 1) bps = 1;
        if (bps > 4) bps = 4;
        agg_grid = nsm * bps;
        if (agg_grid < 1) agg_grid = 148;

        int bpe = 0;
        cudaOccupancyMaxActiveBlocksPerMultiprocessor(&bpe, edge_kernel, 256, 0);
        if (bpe < 1) bpe = 1;
        if (bpe > 8) bpe = 8;
        edge_grid = nsm * bpe;
        if (edge_grid < 1) edge_grid = 148;
    }

    size_t nd = (size_t)n * D;
    if ((size_t)out_size > nd)
        cudaMemsetAsync(out + nd, 0, ((size_t)out_size - nd) * sizeof(float), 0);

    int ntiles = (n + 1023) / 1024;
    edge_kernel<<<edge_grid, 256>>>(ei, n, E, ntiles);  // whole edge pipeline

    prep_w_kernel<<<64, 256>>>(W);
    cudaFuncSetAttribute(gemm_mma_kernel, cudaFuncAttributeMaxDynamicSharedMemorySize, GEMM_SMEM);
    gemm_mma_kernel<<<(n + 127) / 128, 256, GEMM_SMEM>>>(x, n);

    agg_kernel<<<agg_grid, 256>>>(out, x, gamma, beta, n);  // + BN + stats + epilogue
}

// round 16
// speedup vs baseline: 1.0743x; 1.0743x over previous
#include <cuda_runtime.h>
#include <cuda_bf16.h>
#include <cuda_fp16.h>
#include <cstdint>

#define D 128
#define NMAX 100000
#define EMAX 800000
#define NBMAX 128   // ceil(NMAX/1024)
#define WPAD 136    // padded bf16 row stride (272B): conflict-free fragments

// -------- scratch (device globals; no allocations allowed) --------
__device__ __half g_hh[(size_t)NMAX * D];  // x @ W^T, fp16 (256B/row)
__device__ __half g_agg[(size_t)NMAX * D]; // pre-BN aggregate, fp16
__device__ float g_deg[NMAX];
__device__ float g_dinv[NMAX];
__device__ int   g_rows[EMAX];
__device__ int   g_cols[EMAX];
__device__ int   g_sr[EMAX];              // row ids sorted by destination col
__device__ int   g_off[NMAX + 1];         // CSR offsets (by col)
__device__ int   g_cursor[NMAX];
__device__ int   g_bsum[NBMAX];
__device__ int   g_bpre[NBMAX];
__device__ float g_sum[D];
__device__ float g_sumsq[D];
__device__ float g_mean[D];
__device__ float g_scale[D];
__device__ int   g_is64;
__device__ int   g_ctrA;                  // scanA last-block counter
__device__ int   g_ctrB;                  // agg grid-barrier counter
__device__ volatile int g_go;             // agg grid-barrier release flag
__device__ __align__(16) __nv_bfloat16 g_whi[128 * WPAD];  // W hi, padded
__device__ __align__(16) __nv_bfloat16 g_wlo[128 * WPAD];  // W lo, padded

// -------- zero scratch + warp-parallel edge-dtype detect + ctr reset ------
// Node ids < 2^31. int64 layout => every odd 32-bit word (high half) is 0.
__global__ void zero_kernel(const unsigned int* __restrict__ w, int n) {
    int i = blockIdx.x * blockDim.x + threadIdx.x;
    if (i < n) g_deg[i] = 0.f;
    if (i < D) { g_sum[i] = 0.f; g_sumsq[i] = 0.f; }
    if (blockIdx.x == 0 && threadIdx.x < 32) {
        int lane = threadIdx.x;
        unsigned int a = w[2 * lane + 1];
        unsigned int b = w[2 * lane + 65];
        unsigned int nz = __ballot_sync(0xFFFFFFFFu, (a | b) != 0u);
        if (lane == 0) {
            g_is64 = (nz == 0u) ? 1 : 0;
            g_ctrA = 0; g_ctrB = 0; g_go = 0;
        }
    }
}

// -------- convert edges to int32 staging + fused degree histogram --------
__global__ void convert_kernel(const void* __restrict__ ei, int E) {
    int e = blockIdx.x * blockDim.x + threadIdx.x;
    if (e >= E) return;
    int r, c;
    if (g_is64) {
        const long long* p = (const long long*)ei;
        r = (int)p[e];
        c = (int)p[(size_t)E + e];
    } else {
        const int* p = (const int*)ei;
        r = p[e];
        c = p[(size_t)E + e];
    }
    g_rows[e] = r;
    g_cols[e] = c;
    atomicAdd(&g_deg[c], 1.0f);
}

// ======== coalesced scan of degrees; last block scans the block sums =======
__global__ void scanA_kernel(int n) {
    __shared__ int wsum[8];
    __shared__ int slast;
    __shared__ int sscan[NBMAX];
    int t = threadIdx.x;
    int lane = t & 31, w = t >> 5;
    int base = blockIdx.x * 1024 + t * 4;

    int v0 = 0, v1 = 0, v2 = 0, v3 = 0;
    if (base + 3 < n) {
        float4 f = *(const float4*)(g_deg + base);
        v0 = (int)f.x; v1 = (int)f.y; v2 = (int)f.z; v3 = (int)f.w;
    } else {
        if (base + 0 < n) v0 = (int)g_deg[base + 0];
        if (base + 1 < n) v1 = (int)g_deg[base + 1];
        if (base + 2 < n) v2 = (int)g_deg[base + 2];
        if (base + 3 < n) v3 = (int)g_deg[base + 3];
    }
    int ts = v0 + v1 + v2 + v3;

    int incl = ts;
    #pragma unroll
    for (int d = 1; d < 32; d <<= 1) {
        int u = __shfl_up_sync(0xFFFFFFFFu, incl, d);
        if (lane >= d) incl += u;
    }
    if (lane == 31) wsum[w] = incl;
    __syncthreads();
    if (t == 0) {
        int run = 0;
        #pragma unroll
        for (int i = 0; i < 8; i++) { int x = wsum[i]; wsum[i] = run; run += x; }
    }
    __syncthreads();

    int ex = wsum[w] + incl - ts;
    if (base + 3 < n) {
        *(int4*)(g_off + base) = make_int4(ex, ex + v0, ex + v0 + v1, ex + v0 + v1 + v2);
    } else {
        if (base + 0 < n) g_off[base + 0] = ex;
        if (base + 1 < n) g_off[base + 1] = ex + v0;
        if (base + 2 < n) g_off[base + 2] = ex + v0 + v1;
        if (base + 3 < n) g_off[base + 3] = ex + v0 + v1 + v2;
    }
    if (t == 255) {
        g_bsum[blockIdx.x] = wsum[7] + incl;
        __threadfence();
        slast = (atomicAdd(&g_ctrA, 1) == (int)gridDim.x - 1) ? 1 : 0;
    }
    __syncthreads();
    if (slast) {   // fused "scanB": last-finishing block scans <=128 sums
        int nb = gridDim.x;
        if (t < nb) sscan[t] = g_bsum[t];
        __syncthreads();
        if (t == 0) {
            int run = 0;
            for (int i = 0; i < nb; i++) { int v = sscan[i]; sscan[i] = run; run += v; }
        }
        __syncthreads();
        if (t < nb) g_bpre[t] = sscan[t];
    }
}

// Phase C: add block prefixes, init cursor, fused dinv. All coalesced.
__global__ void scanC_kernel(int n, int E) {
    int i = blockIdx.x * blockDim.x + threadIdx.x;
    if (i < n) {
        int off = g_off[i] + g_bpre[i >> 10];
        g_off[i] = off;
        g_cursor[i] = off;
        float d = g_deg[i];
        g_dinv[i] = (d > 0.f) ? rsqrtf(d) : 0.f;
    }
    if (i == 0) g_off[n] = E;
}

// -------- bucket edges by destination col --------
__global__ void bucket_kernel(int E) {
    int e = blockIdx.x * blockDim.x + threadIdx.x;
    if (e >= E) return;
    int c = g_cols[e];
    int pos = atomicAdd(&g_cursor[c], 1);
    g_sr[pos] = g_rows[e];
}

// ======== GEMM via mma.sync bf16 (3-term hi/lo split, fp32 accum) =========
__global__ void prep_w_kernel(const float* __restrict__ W) {
    int i = blockIdx.x * blockDim.x + threadIdx.x;
    if (i >= 128 * 128) return;
    int r = i >> 7, k = i & 127;
    float v = W[i];
    __nv_bfloat16 h = __float2bfloat16(v);
    g_whi[r * WPAD + k] = h;
    g_wlo[r * WPAD + k] = __float2bfloat16(v - __bfloat162float(h));
}

__device__ __forceinline__ void mma16816(float* c, const uint32_t* a,
                                         uint32_t b0, uint32_t b1) {
    asm volatile(
        "mma.sync.aligned.m16n8k16.row.col.f32.bf16.bf16.f32 "
        "{%0,%1,%2,%3}, {%4,%5,%6,%7}, {%8,%9}, {%0,%1,%2,%3};"
        : "+f"(c[0]), "+f"(c[1]), "+f"(c[2]), "+f"(c[3])
        : "r"(a[0]), "r"(a[1]), "r"(a[2]), "r"(a[3]), "r"(b0), "r"(b1));
}

#define SM_WHI 0
#define SM_WLO (128 * WPAD)
#define SM_XHI (2 * 128 * WPAD)
#define SM_XLO (3 * 128 * WPAD)
#define GEMM_SMEM (4 * 128 * WPAD * 2)   // 139264 bytes

__global__ __launch_bounds__(256, 1)
void gemm_mma_kernel(const float* __restrict__ x, int n) {
    extern __shared__ __nv_bfloat16 smem[];
    int t = threadIdx.x;
    int row0 = blockIdx.x * 128;

    {
        const uint4* srcH = (const uint4*)g_whi;
        const uint4* srcL = (const uint4*)g_wlo;
        uint4* dstH = (uint4*)(smem + SM_WHI);
        uint4* dstL = (uint4*)(smem + SM_WLO);
        #pragma unroll
        for (int i = t; i < 2176; i += 256) { dstH[i] = srcH[i]; dstL[i] = srcL[i]; }
    }
    #pragma unroll
    for (int i = t; i < 4096; i += 256) {
        int r = i >> 5, c4 = (i & 31) << 2;
        int gr = row0 + r;
        float4 v = make_float4(0.f, 0.f, 0.f, 0.f);
        if (gr < n) v = *(const float4*)(x + (size_t)gr * D + c4);
        __nv_bfloat16 h0 = __float2bfloat16(v.x), h1 = __float2bfloat16(v.y);
        __nv_bfloat16 h2 = __float2bfloat16(v.z), h3 = __float2bfloat16(v.w);
        __nv_bfloat162* ph = (__nv_bfloat162*)(smem + SM_XHI + r * WPAD + c4);
        __nv_bfloat162* pl = (__nv_bfloat162*)(smem + SM_XLO + r * WPAD + c4);
        ph[0] = __nv_bfloat162(h0, h1);
        ph[1] = __nv_bfloat162(h2, h3);
        pl[0] = __nv_bfloat162(__float2bfloat16(v.x - __bfloat162float(h0)),
                               __float2bfloat16(v.y - __bfloat162float(h1)));
        pl[1] = __nv_bfloat162(__float2bfloat16(v.z - __bfloat162float(h2)),
                               __float2bfloat16(v.w - __bfloat162float(h3)));
    }
    __syncthreads();

    int lane = t & 31, wid = t >> 5;
    int wm = wid & 1;
    int wn = wid >> 1;
    int rq = lane >> 2;
    int kq = (lane & 3) << 1;

    float acc[4][4][4] = {};

    #pragma unroll
    for (int ks = 0; ks < 8; ks++) {
        int kb = ks * 16 + kq;
        uint32_t aH[4][4], aL[4][4];
        #pragma unroll
        for (int mi = 0; mi < 4; mi++) {
            int rb = wm * 64 + mi * 16 + rq;
            const __nv_bfloat16* pH = smem + SM_XHI + rb * WPAD + kb;
            const __nv_bfloat16* pL = smem + SM_XLO + rb * WPAD + kb;
            aH[mi][0] = *(const uint32_t*)pH;
            aH[mi][1] = *(const uint32_t*)(pH + 8 * WPAD);
            aH[mi][2] = *(const uint32_t*)(pH + 8);
            aH[mi][3] = *(const uint32_t*)(pH + 8 * WPAD + 8);
            aL[mi][0] = *(const uint32_t*)pL;
            aL[mi][1] = *(const uint32_t*)(pL + 8 * WPAD);
            aL[mi][2] = *(const uint32_t*)(pL + 8);
            aL[mi][3] = *(const uint32_t*)(pL + 8 * WPAD + 8);
        }
        #pragma unroll
        for (int ni = 0; ni < 4; ni++) {
            int nb = wn * 32 + ni * 8 + rq;
            const __nv_bfloat16* pH = smem + SM_WHI + nb * WPAD + kb;
            const __nv_bfloat16* pL = smem + SM_WLO + nb * WPAD + kb;
            uint32_t bH0 = *(const uint32_t*)pH;
            uint32_t bH1 = *(const uint32_t*)(pH + 8);
            uint32_t bL0 = *(const uint32_t*)pL;
            uint32_t bL1 = *(const uint32_t*)(pL + 8);
            #pragma unroll
            for (int mi = 0; mi < 4; mi++) {
                mma16816(acc[mi][ni], aH[mi], bH0, bH1);
                mma16816(acc[mi][ni], aH[mi], bL0, bL1);
                mma16816(acc[mi][ni], aL[mi], bH0, bH1);
            }
        }
    }

    // epilogue: store fp16 (halves agg's read traffic)
    #pragma unroll
    for (int mi = 0; mi < 4; mi++) {
        int r0 = row0 + wm * 64 + mi * 16 + rq;
        #pragma unroll
        for (int ni = 0; ni < 4; ni++) {
            int cc = wn * 32 + ni * 8 + kq;
            if (r0 < n) {
                __half2 hv = __floats2half2_rn(acc[mi][ni][0], acc[mi][ni][1]);
                *(__half2*)(g_hh + (size_t)r0 * D + cc) = hv;
            }
            if (r0 + 8 < n) {
                __half2 hv = __floats2half2_rn(acc[mi][ni][2], acc[mi][ni][3]);
                *(__half2*)(g_hh + (size_t)(r0 + 8) * D + cc) = hv;
            }
        }
    }
}

// ==== persistent agg: gather + BN sums + grid barrier + stats + epilogue ===
// Phase 1 stores the pre-BN aggregate as fp16 (g_agg, 25.6MB -> L2-hot for
// phase 2 and half the write traffic). BN stats come from the fp32 regs.
// Phase 2 reads g_agg + x, applies BN/relu/residual, writes fp32 out once.
__global__ __launch_bounds__(256, 4)
void agg_kernel(float* __restrict__ out, const float* __restrict__ x,
                const float* __restrict__ gamma, const float* __restrict__ beta,
                int n) {
    __shared__ float ss[8][128];
    __shared__ float sq[8][128];
    __shared__ int slast;
    int t = threadIdx.x;
    int w = t >> 5, lane = t & 31;
    int stride = gridDim.x * 8;
    int c4 = lane << 2;

    // ---- phase 1: gather + per-warp BN partial sums ----
    float4 csum = make_float4(0.f, 0.f, 0.f, 0.f);
    float4 csq  = make_float4(0.f, 0.f, 0.f, 0.f);

    for (int c = blockIdx.x * 8 + w; c < n; c += stride) {
        int beg = g_off[c], end = g_off[c + 1];
        float dc = g_dinv[c];
        float4 acc = make_float4(0.f, 0.f, 0.f, 0.f);

        int j = beg;
        for (; j + 1 < end; j += 2) {
            int r0 = g_sr[j], r1 = g_sr[j + 1];
            float n0 = dc * g_dinv[r0];
            float n1 = dc * g_dinv[r1];
            uint2 u0 = *((const uint2*)(g_hh + ((size_t)r0 << 7)) + lane);
            uint2 u1 = *((const uint2*)(g_hh + ((size_t)r1 << 7)) + lane);
            float2 a0 = __half22float2(*(__half2*)&u0.x);
            float2 b0 = __half22float2(*(__half2*)&u0.y);
            float2 a1 = __half22float2(*(__half2*)&u1.x);
            float2 b1 = __half22float2(*(__half2*)&u1.y);
            acc.x += a0.x * n0 + a1.x * n1;
            acc.y += a0.y * n0 + a1.y * n1;
            acc.z += b0.x * n0 + b1.x * n1;
            acc.w += b0.y * n0 + b1.y * n1;
        }
        if (j < end) {
            int r0 = g_sr[j];
            float n0 = dc * g_dinv[r0];
            uint2 u0 = *((const uint2*)(g_hh + ((size_t)r0 << 7)) + lane);
            float2 a0 = __half22float2(*(__half2*)&u0.x);
            float2 b0 = __half22float2(*(__half2*)&u0.y);
            acc.x += a0.x * n0; acc.y += a0.y * n0;
            acc.z += b0.x * n0; acc.w += b0.y * n0;
        }
        // store pre-BN aggregate as fp16
        uint2 st;
        *(__half2*)&st.x = __floats2half2_rn(acc.x, acc.y);
        *(__half2*)&st.y = __floats2half2_rn(acc.z, acc.w);
        *((uint2*)(g_agg + ((size_t)c << 7)) + lane) = st;

        csum.x += acc.x; csum.y += acc.y; csum.z += acc.z; csum.w += acc.w;
        csq.x += acc.x * acc.x; csq.y += acc.y * acc.y;
        csq.z += acc.z * acc.z; csq.w += acc.w * acc.w;
    }

    ss[w][c4 + 0] = csum.x; ss[w][c4 + 1] = csum.y;
    ss[w][c4 + 2] = csum.z; ss[w][c4 + 3] = csum.w;
    sq[w][c4 + 0] = csq.x;  sq[w][c4 + 1] = csq.y;
    sq[w][c4 + 2] = csq.z;  sq[w][c4 + 3] = csq.w;
    __syncthreads();
    if (t < 128) {
        float s = 0.f, s2 = 0.f;
        #pragma unroll
        for (int i = 0; i < 8; i++) { s += ss[i][t]; s2 += sq[i][t]; }
        atomicAdd(&g_sum[t], s);
        atomicAdd(&g_sumsq[t], s2);
    }

    // ---- grid barrier (all blocks resident by construction) ----
    __threadfence();
    __syncthreads();
    if (t == 0)
        slast = (atomicAdd(&g_ctrB, 1) == (int)gridDim.x - 1) ? 1 : 0;
    __syncthreads();
    if (slast) {
        if (t < 128) {
            float inv_n = 1.0f / (float)n;
            float mean = g_sum[t] * inv_n;
            float var = g_sumsq[t] * inv_n - mean * mean;
            g_mean[t] = mean;               // linear bias cancels via mean subtraction
            g_scale[t] = rsqrtf(var + 1e-5f) * gamma[t];
        }
        __threadfence();
        __syncthreads();
        if (t == 0) g_go = 1;
    }
    if (t == 0) { while (g_go == 0) __nanosleep(64); }
    __syncthreads();
    __threadfence();   // acquire: order g_mean/g_scale reads after flag

    // ---- phase 2: epilogue (g_agg L2-hot) ----
    float4 mn = *(const float4*)(g_mean + c4);
    float4 sc = *(const float4*)(g_scale + c4);
    float4 bt = *(const float4*)(beta + c4);
    for (int c = blockIdx.x * 8 + w; c < n; c += stride) {
        uint2 u = *((const uint2*)(g_agg + ((size_t)c << 7)) + lane);
        float2 p = __half22float2(*(__half2*)&u.x);
        float2 q = __half22float2(*(__half2*)&u.y);
        float4 xv = *(const float4*)(x + (size_t)c * D + c4);
        float4 a;
        a.x = fmaxf((p.x - mn.x) * sc.x + bt.x, 0.f) + xv.x;
        a.y = fmaxf((p.y - mn.y) * sc.y + bt.y, 0.f) + xv.y;
        a.z = fmaxf((q.x - mn.z) * sc.z + bt.z, 0.f) + xv.z;
        a.w = fmaxf((q.y - mn.w) * sc.w + bt.w, 0.f) + xv.w;
        *(float4*)(out + ((size_t)c << 7) + c4) = a;
    }
}

extern "C" void kernel_launch(void* const* d_in, const int* in_sizes, int n_in,
                              void* d_out, int out_size) {
    const float* x     = (const float*)d_in[0];
    const void*  ei    = d_in[1];
    const float* W     = (const float*)d_in[2];
    const float* gamma = (const float*)d_in[4];
    const float* beta  = (const float*)d_in[5];
    int n = in_sizes[0] / D;
    int E = in_sizes[1] / 2;
    float* out = (float*)d_out;

    // residency-safe grid for the persistent agg kernel
    static int agg_grid = 0;
    if (agg_grid == 0) {
        int dev = 0, nsm = 0, bps = 0;
        cudaGetDevice(&dev);
        cudaDeviceGetAttribute(&nsm, cudaDevAttrMultiProcessorCount, dev);
        cudaOccupancyMaxActiveBlocksPerMultiprocessor(&bps, agg_kernel, 256, 0);
        if (bps < 1) bps = 1;
        if (bps > 4) bps = 4;
        agg_grid = nsm * bps;
        if (agg_grid < 1) agg_grid = 148;
    }

    size_t nd = (size_t)n * D;
    if ((size_t)out_size > nd)
        cudaMemsetAsync(out + nd, 0, ((size_t)out_size - nd) * sizeof(float), 0);

    zero_kernel<<<(n + 255) / 256, 256>>>((const unsigned int*)ei, n);  // + detect + ctrs
    convert_kernel<<<(E + 255) / 256, 256>>>(ei, E);                    // + degree
    int nb = (n + 1023) / 1024;
    scanA_kernel<<<nb, 256>>>(n);                                       // + block-sum scan
    scanC_kernel<<<(n + 255) / 256, 256>>>(n, E);                       // + dinv
    bucket_kernel<<<(E + 255) / 256, 256>>>(E);

    prep_w_kernel<<<64, 256>>>(W);
    cudaFuncSetAttribute(gemm_mma_kernel, cudaFuncAttributeMaxDynamicSharedMemorySize, GEMM_SMEM);
    gemm_mma_kernel<<<(n + 127) / 128, 256, GEMM_SMEM>>>(x, n);

    agg_kernel<<<agg_grid, 256>>>(out, x, gamma, beta, n);  // + BN + stats + epilogue
}